// round 10
// baseline (speedup 1.0000x reference)
#include <cuda_runtime.h>
#include <math.h>
#include <stdint.h>

#define SQ   1024
#define HID  768
#define NHD  12
#define DH   64
#define NG   4
#define NLAY 4
#define NEXP 8
#define FFD  3072
#define NVOC 50257
#define QKVN 1280   // 768 + 256 + 256

// ---------------- scratch (device globals; no allocation) ----------------
__device__ float g_h[SQ * HID];
__device__ float g_res[SQ * HID];
__device__ float g_qkv[SQ * QKVN];
__device__ float g_bqkv[NLAY * QKVN];
__device__ float g_h1[2 * SQ * FFD];
__device__ float g_eo[2 * SQ * HID];
__device__ float g_gates[SQ * 2];
__device__ int   g_texp[SQ * 2];
__device__ int   g_tlocal[SQ * 2];
__device__ int   g_tslot[SQ * 2];
__device__ int   g_cnt[NEXP];
__device__ int   g_offs[NEXP];
__device__ int   g_perm[2 * SQ];
__device__ int   g_loads[NLAY * NEXP];

// packed tf32 hi/lo buffers (uint4 = hi[k],hi[k+4],lo[k],lo[k+4])
__device__ uint4 g_wqkv_p[NLAY * (HID/16) * 8 * QKVN];          // 31.5 MB
__device__ uint4 g_fc1_p [NLAY * NEXP * (HID/16) * 8 * FFD];    // 604 MB
__device__ uint4 g_fc2_p [NLAY * NEXP * (FFD/16) * 8 * HID];    // 604 MB
__device__ uint4 g_ow_p  [(HID/16) * 8 * NVOC];                 // 308 MB
__device__ uint4 g_hp    [SQ * (HID/2)];                        // 6.3 MB
__device__ uint4 g_h1p   [2 * SQ * (FFD/2)];                    // 50 MB

// ---------------- tf32 helpers ----------------
__device__ __forceinline__ uint32_t f2tf(float x) {
    uint32_t r;
    asm("cvt.rna.tf32.f32 %0, %1;" : "=r"(r) : "f"(x));
    return r;
}

__device__ __forceinline__ void mma_tf32(float c[4],
                                         uint32_t a0, uint32_t a1, uint32_t a2, uint32_t a3,
                                         uint32_t b0, uint32_t b1) {
    asm volatile(
        "mma.sync.aligned.m16n8k8.row.col.f32.tf32.tf32.f32 "
        "{%0,%1,%2,%3}, {%4,%5,%6,%7}, {%8,%9}, {%0,%1,%2,%3};"
        : "+f"(c[0]), "+f"(c[1]), "+f"(c[2]), "+f"(c[3])
        : "r"(a0), "r"(a1), "r"(a2), "r"(a3), "r"(b0), "r"(b1));
}

__device__ __forceinline__ uint4 tf_pack(float v0, float v4) {
    uint4 p;
    p.x = f2tf(v0);
    p.y = f2tf(v4);
    p.z = f2tf(v0 - __uint_as_float(p.x));
    p.w = f2tf(v4 - __uint_as_float(p.y));
    return p;
}

// ---------------- embedding ----------------
__global__ void embed_kernel(const int* __restrict__ ids,
                             const float* __restrict__ emb,
                             const float* __restrict__ pos,
                             float* __restrict__ h) {
    int s = blockIdx.x;
    int id = ids[s];
    for (int c = threadIdx.x; c < HID; c += blockDim.x)
        h[(size_t)s * HID + c] = emb[(size_t)id * HID + c] + pos[(size_t)s * HID + c];
}

// ---------------- weight packing ----------------
// pack B [K][N] (row-major fp32) into P[k16][j][n] uint4, batched over z
__global__ __launch_bounds__(256) void pack_w_batch(
    const float* __restrict__ B, uint4* __restrict__ P, int K, int N,
    size_t sIn, size_t sOut)
{
    int b = blockIdx.z;
    const float* Bb = B + (size_t)b * sIn;
    uint4* Pb = P + (size_t)b * sOut;
    size_t total = (size_t)(K / 16) * 8 * N;
    for (size_t u = (size_t)blockIdx.x * 256 + threadIdx.x; u < total;
         u += (size_t)gridDim.x * 256) {
        int n   = (int)(u % (size_t)N);
        int j   = (int)((u / (size_t)N) & 7);
        int k16 = (int)(u / ((size_t)N * 8));
        int k = k16 * 16 + ((j >> 2) << 3) + (j & 3);
        Pb[u] = tf_pack(Bb[(size_t)k * N + n], Bb[(size_t)(k + 4) * N + n]);
    }
}

// fused qw|kw|vw pack into [l][k16][j][n]
__global__ __launch_bounds__(256) void pack_qkv_wp(
    const float* __restrict__ qw, const float* __restrict__ kw,
    const float* __restrict__ vw, uint4* __restrict__ P)
{
    int l = blockIdx.z;
    const size_t total = (size_t)(HID / 16) * 8 * QKVN;
    uint4* Pb = P + (size_t)l * total;
    for (size_t u = (size_t)blockIdx.x * 256 + threadIdx.x; u < total;
         u += (size_t)gridDim.x * 256) {
        int n   = (int)(u % QKVN);
        int j   = (int)((u / QKVN) & 7);
        int k16 = (int)(u / ((size_t)QKVN * 8));
        int k = k16 * 16 + ((j >> 2) << 3) + (j & 3);
        float v0, v4;
        if (n < HID) {
            v0 = qw[(size_t)l * HID * HID + (size_t)k * HID + n];
            v4 = qw[(size_t)l * HID * HID + (size_t)(k + 4) * HID + n];
        } else if (n < HID + 256) {
            int nn = n - HID;
            v0 = kw[(size_t)l * HID * 256 + (size_t)k * 256 + nn];
            v4 = kw[(size_t)l * HID * 256 + (size_t)(k + 4) * 256 + nn];
        } else {
            int nn = n - HID - 256;
            v0 = vw[(size_t)l * HID * 256 + (size_t)k * 256 + nn];
            v4 = vw[(size_t)l * HID * 256 + (size_t)(k + 4) * 256 + nn];
        }
        Pb[u] = tf_pack(v0, v4);
    }
}

__global__ void pack_qkv_b(const float* __restrict__ qb, const float* __restrict__ kb,
                           const float* __restrict__ vb, float* __restrict__ bqkv)
{
    int idx = blockIdx.x * 256 + threadIdx.x;
    if (idx >= NLAY * QKVN) return;
    int l = idx / QKVN, j = idx % QKVN;
    float v;
    if (j < HID)            v = qb[l * HID + j];
    else if (j < HID + 256) v = kb[l * 256 + (j - HID)];
    else                    v = vb[l * 256 + (j - HID - 256)];
    bqkv[idx] = v;
}

// pack activations A [rows][cols] into P[row][cols/2] uint4 ([row][k16][j])
__global__ __launch_bounds__(256) void pack_act(
    const float* __restrict__ A, uint4* __restrict__ P, int total, int colsHalf, int cols)
{
    int u = blockIdx.x * 256 + threadIdx.x;
    if (u >= total) return;
    int row = u / colsHalf;
    int rem = u % colsHalf;
    int k16 = rem >> 3, j = rem & 7;
    int k = k16 * 16 + ((j >> 2) << 3) + (j & 3);
    const float* a = A + (size_t)row * cols;
    P[u] = tf_pack(a[k], a[k + 4]);
}

#define ASTG 576            // 64 rows * 9 uint4
#define BSTG 1152           // 128 rows * 9 uint4
#define GEMM_SMEM (2 * (ASTG + BSTG) * 16)   // double-buffered, bytes (55296)

// ---------------- 3xTF32 GEMM on pre-packed operands ----------------
// A packed: [row][K/16][8] uint4 (ldaU = row stride in uint4)
// B packed: [K/16][8][N] uint4
template<bool GELU, bool EXPERT, bool GATHER>
__global__ __launch_bounds__(256, 2) void mma_gemm(
    const uint4* __restrict__ Ap, const uint4* __restrict__ Bp,
    const float* __restrict__ bias, float* __restrict__ C,
    int M, int N, int K, int ldaU, int ldc,
    const int* __restrict__ perm, const int* __restrict__ offs,
    const int* __restrict__ cnts, size_t strideBU, size_t strideBias)
{
    extern __shared__ uint4 sm4[];
    uint4* AP = sm4;                 // [2][ASTG]
    uint4* BP = sm4 + 2 * ASTG;      // [2][BSTG]

    int mcount = M, base = 0;
    if (EXPERT) {
        int e = blockIdx.z;
        mcount = cnts[e];
        base   = offs[e];
        Bp    += (size_t)e * strideBU;
        bias  += (size_t)e * strideBias;
    }
    int m0 = blockIdx.y * 64;
    if (m0 >= mcount) return;
    int n0 = blockIdx.x * 128;

    int tid = threadIdx.x, lane = tid & 31, warp = tid >> 5;
    int wm = (warp & 1) * 32;        // warp M offset (0 or 32)
    int wn = (warp >> 1) * 32;       // warp N offset (0,32,64,96)

    // producer A (threads 0..127): row = tid>>1 (0..63), aKK = tid&1 (j base)
    int aRow = tid >> 1;
    int aKK  = tid & 1;
    bool aprod = (tid < 128);
    bool aok = aprod && (m0 + aRow < mcount);
    const uint4* aptr = Ap;
    if (aok) {
        int phys = GATHER ? perm[base + m0 + aRow]
                          : (EXPERT ? base + m0 + aRow : m0 + aRow);
        aptr = Ap + (size_t)phys * (size_t)ldaU;
    }
    // producer B (all threads): n = tid&127, kq0 = tid>>7
    int bN   = tid & 127;
    int bKQ0 = tid >> 7;
    int gn   = n0 + bN;
    bool bok = (gn < N);

    float c[2][4][4];
#pragma unroll
    for (int i = 0; i < 2; i++)
#pragma unroll
        for (int j = 0; j < 4; j++)
#pragma unroll
            for (int q = 0; q < 4; q++) c[i][j][q] = 0.f;

    const uint4 zero4 = make_uint4(0u, 0u, 0u, 0u);
    uint4 stA4[4], stB4[4];

    // ---- load tile 0 ----
    if (aprod) {
#pragma unroll
        for (int q = 0; q < 4; q++)
            stA4[q] = aok ? aptr[aKK * 4 + q] : zero4;
    }
#pragma unroll
    for (int j = 0; j < 4; j++) {
        int kq = bKQ0 + 2 * j;
        stB4[j] = bok ? Bp[(size_t)kq * (size_t)N + gn] : zero4;
    }
    // ---- store tile 0 to stage 0 ----
    if (aprod) {
#pragma unroll
        for (int q = 0; q < 4; q++)
            AP[aRow * 9 + aKK * 4 + q] = stA4[q];
    }
#pragma unroll
    for (int j = 0; j < 4; j++) {
        int kq = bKQ0 + 2 * j;
        BP[bN * 9 + kq] = stB4[j];
    }
    __syncthreads();

    int buf = 0;
    int nK16 = K >> 4;
    for (int k16 = 0; k16 < nK16; k16++) {
        bool has_next = (k16 + 1 < nK16);
        // ---- issue GLD for next tile ----
        if (has_next) {
            if (aprod) {
#pragma unroll
                for (int q = 0; q < 4; q++)
                    stA4[q] = aok ? aptr[(k16 + 1) * 8 + aKK * 4 + q] : zero4;
            }
#pragma unroll
            for (int j = 0; j < 4; j++) {
                int kq = bKQ0 + 2 * j;
                stB4[j] = bok ? Bp[((size_t)(k16 + 1) * 8 + kq) * (size_t)N + gn] : zero4;
            }
        }

        // ---- MMA on stage buf ----
        const uint4* APc = AP + buf * ASTG;
        const uint4* BPc = BP + buf * BSTG;
        int ra = lane >> 2;
        int q  = lane & 3;
#pragma unroll
        for (int kk = 0; kk < 2; kk++) {
            int kkq = kk * 4 + q;
            uint32_t aH[2][4], aL[2][4];
#pragma unroll
            for (int fm = 0; fm < 2; fm++) {
                int m = wm + fm * 16 + ra;
                uint4 f0 = APc[m * 9 + kkq];
                uint4 f1 = APc[(m + 8) * 9 + kkq];
                aH[fm][0] = f0.x; aH[fm][1] = f1.x;
                aH[fm][2] = f0.y; aH[fm][3] = f1.y;
                aL[fm][0] = f0.z; aL[fm][1] = f1.z;
                aL[fm][2] = f0.w; aL[fm][3] = f1.w;
            }
#pragma unroll
            for (int fn = 0; fn < 4; fn++) {
                int n = wn + fn * 8 + ra;
                uint4 fb = BPc[n * 9 + kkq];
#pragma unroll
                for (int fm = 0; fm < 2; fm++) {
                    mma_tf32(c[fm][fn], aL[fm][0], aL[fm][1], aL[fm][2], aL[fm][3], fb.x, fb.y);
                    mma_tf32(c[fm][fn], aH[fm][0], aH[fm][1], aH[fm][2], aH[fm][3], fb.z, fb.w);
                    mma_tf32(c[fm][fn], aH[fm][0], aH[fm][1], aH[fm][2], aH[fm][3], fb.x, fb.y);
                }
            }
        }

        // ---- store next tile into stage buf^1 ----
        if (has_next) {
            uint4* APn = AP + (buf ^ 1) * ASTG;
            uint4* BPn = BP + (buf ^ 1) * BSTG;
            if (aprod) {
#pragma unroll
                for (int qq = 0; qq < 4; qq++)
                    APn[aRow * 9 + aKK * 4 + qq] = stA4[qq];
            }
#pragma unroll
            for (int j = 0; j < 4; j++) {
                int kq = bKQ0 + 2 * j;
                BPn[bN * 9 + kq] = stB4[j];
            }
        }
        __syncthreads();
        buf ^= 1;
    }

    // epilogue
#pragma unroll
    for (int fm = 0; fm < 2; fm++) {
#pragma unroll
        for (int half = 0; half < 2; half++) {
            int mrel = m0 + wm + fm * 16 + (lane >> 2) + half * 8;
            if (mrel >= mcount) continue;
            size_t crow = (size_t)(EXPERT ? base + mrel : mrel) * (size_t)ldc;
#pragma unroll
            for (int fn = 0; fn < 4; fn++) {
                int n = n0 + wn + fn * 8 + (lane & 3) * 2;
                float v0 = c[fm][fn][half * 2 + 0];
                float v1 = c[fm][fn][half * 2 + 1];
                if (n < N) {
                    float o = v0 + bias[n];
                    if (GELU) o = 0.5f * o * (1.f + erff(o * 0.70710678118654752f));
                    C[crow + n] = o;
                }
                if (n + 1 < N) {
                    float o = v1 + bias[n + 1];
                    if (GELU) o = 0.5f * o * (1.f + erff(o * 0.70710678118654752f));
                    C[crow + n + 1] = o;
                }
            }
        }
    }
}

// ---------------- flash-style GQA attention (fp32, reads combined QKV) ----------------
__global__ __launch_bounds__(256) void attn_kernel(
    const float* __restrict__ qkv, const int* __restrict__ amask,
    float* __restrict__ ao)
{
    const float SCALE = 0.125f;
    int head = blockIdx.y;
    int g    = head / (NHD / NG);
    int q0   = blockIdx.x * 64;

    __shared__ float QsT[64][68];
    __shared__ float KsT[64][33];
    __shared__ float Vs [32][68];
    __shared__ float PsT[32][68];
    __shared__ float Mk [32];

    int tid = threadIdx.x;
#pragma unroll
    for (int i = 0; i < 4; i++) {
        int idx = tid + i * 256;
        int r = idx >> 4;
        int dseg = (idx & 15) * 4;
        float4 qv = *(const float4*)(qkv + (size_t)(q0 + r) * QKVN + head * 64 + dseg);
        QsT[dseg + 0][r] = qv.x; QsT[dseg + 1][r] = qv.y;
        QsT[dseg + 2][r] = qv.z; QsT[dseg + 3][r] = qv.w;
    }

    int rg = tid >> 4, kg = tid & 15;
    int r0 = rg * 4, d0 = kg * 4, j0 = kg * 2;

    float acc[4][4] = {};
    float m[4], l[4];
#pragma unroll
    for (int i = 0; i < 4; i++) { m[i] = -3.0e38f; l[i] = 0.f; }

    for (int kc = 0; kc < 32; kc++) {
        int kbase = kc * 32;
#pragma unroll
        for (int i = 0; i < 2; i++) {
            int idx = tid + i * 256;
            int kk = idx >> 4;
            int dseg = (idx & 15) * 4;
            float4 kv = *(const float4*)(qkv + (size_t)(kbase + kk) * QKVN + HID + g * 64 + dseg);
            KsT[dseg + 0][kk] = kv.x; KsT[dseg + 1][kk] = kv.y;
            KsT[dseg + 2][kk] = kv.z; KsT[dseg + 3][kk] = kv.w;
            float4 vv = *(const float4*)(qkv + (size_t)(kbase + kk) * QKVN + HID + 256 + g * 64 + dseg);
            *(float4*)&Vs[kk][dseg] = vv;
        }
        if (tid < 32) Mk[tid] = (amask[kbase + tid] == 0) ? -3.0e38f : 0.f;
        __syncthreads();

        float s0[4] = {}, s1[4] = {};
#pragma unroll
        for (int d = 0; d < 64; d++) {
            float4 a = *(const float4*)&QsT[d][r0];
            float b0 = KsT[d][j0], b1 = KsT[d][j0 + 1];
            s0[0] += a.x * b0; s1[0] += a.x * b1;
            s0[1] += a.y * b0; s1[1] += a.y * b1;
            s0[2] += a.z * b0; s1[2] += a.z * b1;
            s0[3] += a.w * b0; s1[3] += a.w * b1;
        }
        float mk0 = Mk[j0], mk1 = Mk[j0 + 1];
        float cm[4];
#pragma unroll
        for (int i = 0; i < 4; i++) {
            s0[i] = s0[i] * SCALE + mk0;
            s1[i] = s1[i] * SCALE + mk1;
            cm[i] = fmaxf(s0[i], s1[i]);
        }
#pragma unroll
        for (int o = 1; o < 16; o <<= 1)
#pragma unroll
            for (int i = 0; i < 4; i++)
                cm[i] = fmaxf(cm[i], __shfl_xor_sync(0xffffffffu, cm[i], o));

        float p0[4], p1[4], csum[4];
#pragma unroll
        for (int i = 0; i < 4; i++) {
            float nm = fmaxf(m[i], cm[i]);
            float alpha = expf(m[i] - nm);
            m[i] = nm;
            p0[i] = expf(s0[i] - nm);
            p1[i] = expf(s1[i] - nm);
            csum[i] = p0[i] + p1[i];
            l[i] *= alpha;
#pragma unroll
            for (int j = 0; j < 4; j++) acc[i][j] *= alpha;
        }
#pragma unroll
        for (int o = 1; o < 16; o <<= 1)
#pragma unroll
            for (int i = 0; i < 4; i++)
                csum[i] += __shfl_xor_sync(0xffffffffu, csum[i], o);
#pragma unroll
        for (int i = 0; i < 4; i++) l[i] += csum[i];

#pragma unroll
        for (int i = 0; i < 4; i++) {
            PsT[j0][r0 + i]     = p0[i];
            PsT[j0 + 1][r0 + i] = p1[i];
        }
        __syncthreads();

#pragma unroll
        for (int key = 0; key < 32; key++) {
            float4 pv = *(const float4*)&PsT[key][r0];
            float4 vv = *(const float4*)&Vs[key][d0];
            acc[0][0] += pv.x * vv.x; acc[0][1] += pv.x * vv.y; acc[0][2] += pv.x * vv.z; acc[0][3] += pv.x * vv.w;
            acc[1][0] += pv.y * vv.x; acc[1][1] += pv.y * vv.y; acc[1][2] += pv.y * vv.z; acc[1][3] += pv.y * vv.w;
            acc[2][0] += pv.z * vv.x; acc[2][1] += pv.z * vv.y; acc[2][2] += pv.z * vv.z; acc[2][3] += pv.z * vv.w;
            acc[3][0] += pv.w * vv.x; acc[3][1] += pv.w * vv.y; acc[3][2] += pv.w * vv.z; acc[3][3] += pv.w * vv.w;
        }
        __syncthreads();
    }

#pragma unroll
    for (int i = 0; i < 4; i++) {
        float inv = 1.f / l[i];
        float4 o;
        o.x = acc[i][0] * inv; o.y = acc[i][1] * inv;
        o.z = acc[i][2] * inv; o.w = acc[i][3] * inv;
        *(float4*)(ao + (size_t)(q0 + r0 + i) * HID + head * 64 + d0) = o;
    }
}

// ---------------- layernorm: h = LN(h + res) ----------------
__global__ __launch_bounds__(256) void ln_kernel(float* __restrict__ h,
                                                 const float* __restrict__ res,
                                                 const float* __restrict__ gam,
                                                 const float* __restrict__ bet) {
    int row = blockIdx.x;
    __shared__ float xbuf[HID];
    __shared__ float red[256];
    int tid = threadIdx.x;
    float lsum = 0.f;
    for (int c = tid; c < HID; c += 256) {
        float v = h[(size_t)row * HID + c] + res[(size_t)row * HID + c];
        xbuf[c] = v;
        lsum += v;
    }
    red[tid] = lsum; __syncthreads();
    for (int s = 128; s > 0; s >>= 1) { if (tid < s) red[tid] += red[tid + s]; __syncthreads(); }
    float mean = red[0] / (float)HID;
    __syncthreads();
    float lvar = 0.f;
    for (int c = tid; c < HID; c += 256) { float d = xbuf[c] - mean; lvar += d * d; }
    red[tid] = lvar; __syncthreads();
    for (int s = 128; s > 0; s >>= 1) { if (tid < s) red[tid] += red[tid + s]; __syncthreads(); }
    float rstd = rsqrtf(red[0] / (float)HID + 1e-5f);
    for (int c = tid; c < HID; c += 256)
        h[(size_t)row * HID + c] = (xbuf[c] - mean) * rstd * gam[c] + bet[c];
}

// ---------------- router: top-2 gating ----------------
__global__ __launch_bounds__(256) void router_kernel(
    const float* __restrict__ h, const float* __restrict__ rw,
    const float* __restrict__ rb, float* __restrict__ gates,
    int* __restrict__ texp, int* __restrict__ tlocal, int* __restrict__ cnt)
{
    int t = blockIdx.x;
    int tid = threadIdx.x;
    int e = tid >> 5, lane = tid & 31;
    float sum = 0.f;
    for (int i = lane; i < HID; i += 32)
        sum += h[(size_t)t * HID + i] * rw[i * NEXP + e];
#pragma unroll
    for (int o = 16; o > 0; o >>= 1) sum += __shfl_down_sync(0xffffffffu, sum, o);
    __shared__ float logits[NEXP];
    if (lane == 0) logits[e] = sum + rb[e];
    __syncthreads();
    if (tid == 0) {
        float mx = logits[0];
        for (int i = 1; i < NEXP; i++) mx = fmaxf(mx, logits[i]);
        float ex[NEXP], ssum = 0.f;
        for (int i = 0; i < NEXP; i++) { ex[i] = expf(logits[i] - mx); ssum += ex[i]; }
        float p[NEXP];
        for (int i = 0; i < NEXP; i++) p[i] = ex[i] / ssum;
        int i0 = 0;
        for (int i = 1; i < NEXP; i++) if (p[i] > p[i0]) i0 = i;
        int i1 = (i0 == 0) ? 1 : 0;
        for (int i = 0; i < NEXP; i++) if (i != i0 && p[i] > p[i1]) i1 = i;
        float b = expf(p[i1] - p[i0]);
        float g0 = 1.f / (1.f + b);
        float g1 = b / (1.f + b);
        gates[t * 2] = g0; gates[t * 2 + 1] = g1;
        texp[t * 2] = i0; texp[t * 2 + 1] = i1;
        tlocal[t * 2]     = atomicAdd(&cnt[i0], 1);
        tlocal[t * 2 + 1] = atomicAdd(&cnt[i1], 1);
    }
}

__global__ void zero_cnt_kernel(int* c) { if (threadIdx.x < NEXP) c[threadIdx.x] = 0; }

__global__ __launch_bounds__(256) void assign_kernel(
    const int* __restrict__ cnt, int* __restrict__ offs, int* __restrict__ perm,
    const int* __restrict__ texp, const int* __restrict__ tlocal,
    int* __restrict__ tslot, int* __restrict__ loads)
{
    __shared__ int so[NEXP];
    if (threadIdx.x == 0) {
        int acc = 0;
        for (int e = 0; e < NEXP; e++) {
            so[e] = acc; offs[e] = acc; loads[e] = cnt[e]; acc += cnt[e];
        }
    }
    __syncthreads();
    for (int i = threadIdx.x; i < 2 * SQ; i += blockDim.x) {
        int t = i >> 1;
        int slot = so[texp[i]] + tlocal[i];
        perm[slot] = t;
        tslot[i] = slot;
    }
}

__global__ __launch_bounds__(256) void combine_kernel(
    const float* __restrict__ eo, const float* __restrict__ gates,
    const int* __restrict__ tslot, float* __restrict__ res)
{
    int t = blockIdx.x;
    int s0 = tslot[t * 2], s1 = tslot[t * 2 + 1];
    float g0 = gates[t * 2], g1 = gates[t * 2 + 1];
    for (int c = threadIdx.x; c < HID; c += 256)
        res[(size_t)t * HID + c] = g0 * eo[(size_t)s0 * HID + c] + g1 * eo[(size_t)s1 * HID + c];
}

__global__ void loss_kernel(const int* __restrict__ loads, float* __restrict__ out) {
    int l = threadIdx.x;
    if (l < NLAY) {
        float mean = (float)(2 * SQ) / (float)NEXP;
        float var = 0.f;
        for (int e = 0; e < NEXP; e++) {
            float d = (float)loads[l * NEXP + e] - mean;
            var += d * d;
        }
        var /= (float)(NEXP - 1);
        out[l] = var / (mean * mean);
    }
}

// ---------------- host launch ----------------
extern "C" void kernel_launch(void* const* d_in, const int* in_sizes, int n_in,
                              void* d_out, int out_size) {
    const int*   ids   = (const int*)d_in[0];
    const int*   amask = (const int*)d_in[1];
    const float* emb   = (const float*)d_in[2];
    const float* pos   = (const float*)d_in[3];
    const float* qw    = (const float*)d_in[4];
    const float* qb    = (const float*)d_in[5];
    const float* kw    = (const float*)d_in[6];
    const float* kb    = (const float*)d_in[7];
    const float* vw    = (const float*)d_in[8];
    const float* vb    = (const float*)d_in[9];
    const float* rw    = (const float*)d_in[10];
    const float* rb    = (const float*)d_in[11];
    const float* fc1w  = (const float*)d_in[12];
    const float* fc1b  = (const float*)d_in[13];
    const float* fc2w  = (const float*)d_in[14];
    const float* fc2b  = (const float*)d_in[15];
    const float* lng   = (const float*)d_in[16];
    const float* lnb   = (const float*)d_in[17];
    const float* ow    = (const float*)d_in[18];
    const float* ob    = (const float*)d_in[19];
    float* out = (float*)d_out;

    cudaFuncSetAttribute(mma_gemm<false, false, false>,
                         cudaFuncAttributeMaxDynamicSharedMemorySize, GEMM_SMEM);
    cudaFuncSetAttribute(mma_gemm<true, true, true>,
                         cudaFuncAttributeMaxDynamicSharedMemorySize, GEMM_SMEM);
    cudaFuncSetAttribute(mma_gemm<false, true, false>,
                         cudaFuncAttributeMaxDynamicSharedMemorySize, GEMM_SMEM);

    float *h, *res, *qkv, *bqkv, *h1, *eo, *gates;
    uint4 *wqkv_p, *fc1_p, *fc2_p, *ow_p, *hp, *h1p;
    int *texp, *tlocal, *tslot, *cnt, *offs, *perm, *loads;
    cudaGetSymbolAddress((void**)&h, g_h);
    cudaGetSymbolAddress((void**)&res, g_res);
    cudaGetSymbolAddress((void**)&qkv, g_qkv);
    cudaGetSymbolAddress((void**)&bqkv, g_bqkv);
    cudaGetSymbolAddress((void**)&h1, g_h1);
    cudaGetSymbolAddress((void**)&eo, g_eo);
    cudaGetSymbolAddress((void**)&gates, g_gates);
    cudaGetSymbolAddress((void**)&wqkv_p, g_wqkv_p);
    cudaGetSymbolAddress((void**)&fc1_p, g_fc1_p);
    cudaGetSymbolAddress((void**)&fc2_p, g_fc2_p);
    cudaGetSymbolAddress((void**)&ow_p, g_ow_p);
    cudaGetSymbolAddress((void**)&hp, g_hp);
    cudaGetSymbolAddress((void**)&h1p, g_h1p);
    cudaGetSymbolAddress((void**)&texp, g_texp);
    cudaGetSymbolAddress((void**)&tlocal, g_tlocal);
    cudaGetSymbolAddress((void**)&tslot, g_tslot);
    cudaGetSymbolAddress((void**)&cnt, g_cnt);
    cudaGetSymbolAddress((void**)&offs, g_offs);
    cudaGetSymbolAddress((void**)&perm, g_perm);
    cudaGetSymbolAddress((void**)&loads, g_loads);

    // ---- pre-pack all weights (per-call, deterministic) ----
    pack_qkv_wp<<<dim3(1920, 1, NLAY), 256>>>(qw, kw, vw, wqkv_p);
    pack_qkv_b<<<(NLAY * QKVN + 255) / 256, 256>>>(qb, kb, vb, bqkv);
    pack_w_batch<<<dim3(4608, 1, NLAY * NEXP), 256>>>(
        fc1w, fc1_p, HID, FFD, (size_t)HID * FFD, (size_t)(HID / 16) * 8 * FFD);
    pack_w_batch<<<dim3(4608, 1, NLAY * NEXP), 256>>>(
        fc2w, fc2_p, FFD, HID, (size_t)FFD * HID, (size_t)(FFD / 16) * 8 * HID);
    {
        size_t tot = (size_t)(HID / 16) * 8 * NVOC;
        pack_w_batch<<<dim3((unsigned)((tot + 255) / 256), 1, 1), 256>>>(
            ow, ow_p, HID, NVOC, 0, 0);
    }

    embed_kernel<<<SQ, 256>>>(ids, emb, pos, h);

    const size_t fc1_bstride = (size_t)(HID / 16) * 8 * FFD;
    const size_t fc2_bstride = (size_t)(FFD / 16) * 8 * HID;
    const size_t qkv_bstride = (size_t)(HID / 16) * 8 * QKVN;

    for (int l = 0; l < NLAY; l++) {
        const float* rw_l = rw + (size_t)l * HID * NEXP;
        const float* rb_l = rb + (size_t)l * NEXP;
        const float* fc1b_l = fc1b + (size_t)l * NEXP * FFD;
        const float* fc2b_l = fc2b + (size_t)l * NEXP * HID;

        // pack current h for QKV GEMM
        pack_act<<<SQ * (HID / 2) / 256, 256>>>(h, hp, SQ * (HID / 2), HID / 2, HID);

        // fused QKV projection: [1024,768] @ [768,1280]
        {
            dim3 grid(QKVN / 128, SQ / 64);
            mma_gemm<false, false, false><<<grid, 256, GEMM_SMEM>>>(
                hp, wqkv_p + (size_t)l * qkv_bstride, bqkv + (size_t)l * QKVN,
                qkv, SQ, QKVN, HID, HID / 2, QKVN, nullptr, nullptr, nullptr, 0, 0);
        }

        attn_kernel<<<dim3(SQ / 64, NHD), 256>>>(qkv, amask, res);
        ln_kernel<<<SQ, 256>>>(h, res, lng, lnb);

        zero_cnt_kernel<<<1, 32>>>(cnt);
        router_kernel<<<SQ, 256>>>(h, rw_l, rb_l, gates, texp, tlocal, cnt);
        assign_kernel<<<1, 256>>>(cnt, offs, perm, texp, tlocal, tslot, loads + l * NEXP);

        // re-pack post-attention h for fc1
        pack_act<<<SQ * (HID / 2) / 256, 256>>>(h, hp, SQ * (HID / 2), HID / 2, HID);

        {   // fc1 + gelu (gathered rows)
            dim3 grid(FFD / 128, SQ / 64, NEXP);
            mma_gemm<true, true, true><<<grid, 256, GEMM_SMEM>>>(
                hp, fc1_p + (size_t)l * NEXP * fc1_bstride, fc1b_l, h1,
                SQ, FFD, HID, HID / 2, FFD,
                perm, offs, cnt, fc1_bstride, (size_t)FFD);
        }

        // pack h1 for fc2
        pack_act<<<2 * SQ * (FFD / 2) / 256, 256>>>(h1, h1p, 2 * SQ * (FFD / 2), FFD / 2, FFD);

        {   // fc2 (contiguous slots)
            dim3 grid(HID / 128, SQ / 64, NEXP);
            mma_gemm<false, true, false><<<grid, 256, GEMM_SMEM>>>(
                h1p, fc2_p + (size_t)l * NEXP * fc2_bstride, fc2b_l, eo,
                SQ, HID, FFD, FFD / 2, HID,
                nullptr, offs, cnt, fc2_bstride, (size_t)HID);
        }
        combine_kernel<<<SQ, 256>>>(eo, gates, tslot, res);
        ln_kernel<<<SQ, 256>>>(h, res, lng, lnb);
    }

    // final pack + logits GEMM
    pack_act<<<SQ * (HID / 2) / 256, 256>>>(h, hp, SQ * (HID / 2), HID / 2, HID);
    {
        dim3 grid((NVOC + 127) / 128, SQ / 64);
        mma_gemm<false, false, false><<<grid, 256, GEMM_SMEM>>>(
            hp, ow_p, ob, out, SQ, NVOC, HID, HID / 2, NVOC,
            nullptr, nullptr, nullptr, 0, 0);
    }
    loss_kernel<<<1, 32>>>(loads, out + ((size_t)out_size - NLAY));
}

// round 11
// speedup vs baseline: 1.2904x; 1.2904x over previous
#include <cuda_runtime.h>
#include <math.h>
#include <stdint.h>

#define SQ   1024
#define HID  768
#define NHD  12
#define DH   64
#define NG   4
#define NLAY 4
#define NEXP 8
#define FFD  3072
#define NVOC 50257
#define QKVN 1280   // 768 + 256 + 256

// ---------------- scratch (device globals; no allocation) ----------------
__device__ float g_h[SQ * HID];
__device__ float g_res[SQ * HID];
__device__ float g_qkv[SQ * QKVN];
__device__ float g_wqkv[NLAY * HID * QKVN];
__device__ float g_bqkv[NLAY * QKVN];
__device__ float g_h1[2 * SQ * FFD];
__device__ float g_eo[2 * SQ * HID];
__device__ float g_gates[SQ * 2];
__device__ int   g_texp[SQ * 2];
__device__ int   g_tlocal[SQ * 2];
__device__ int   g_tslot[SQ * 2];
__device__ int   g_cnt[NEXP];
__device__ int   g_offs[NEXP];
__device__ int   g_perm[2 * SQ];
__device__ int   g_loads[NLAY * NEXP];

// ---------------- embedding ----------------
__global__ void embed_kernel(const int* __restrict__ ids,
                             const float* __restrict__ emb,
                             const float* __restrict__ pos,
                             float* __restrict__ h) {
    int s = blockIdx.x;
    int id = ids[s];
    for (int c = threadIdx.x; c < HID; c += blockDim.x)
        h[(size_t)s * HID + c] = emb[(size_t)id * HID + c] + pos[(size_t)s * HID + c];
}

// ---------------- pack qw|kw|vw -> wqkv ----------------
__global__ __launch_bounds__(256) void pack_qkv_w(
    const float* __restrict__ qw, const float* __restrict__ kw,
    const float* __restrict__ vw, float* __restrict__ wqkv)
{
    size_t idx = (size_t)blockIdx.x * 256 + threadIdx.x;
    if (idx >= (size_t)NLAY * HID * QKVN) return;
    int j = (int)(idx % QKVN);
    size_t li = idx / QKVN;            // l*HID + i
    float v;
    if (j < HID)            v = qw[li * HID + j];
    else if (j < HID + 256) v = kw[li * 256 + (j - HID)];
    else                    v = vw[li * 256 + (j - HID - 256)];
    wqkv[idx] = v;
}

__global__ void pack_qkv_b(const float* __restrict__ qb, const float* __restrict__ kb,
                           const float* __restrict__ vb, float* __restrict__ bqkv)
{
    int idx = blockIdx.x * 256 + threadIdx.x;
    if (idx >= NLAY * QKVN) return;
    int l = idx / QKVN, j = idx % QKVN;
    float v;
    if (j < HID)            v = qb[l * HID + j];
    else if (j < HID + 256) v = kb[l * 256 + (j - HID)];
    else                    v = vb[l * 256 + (j - HID - 256)];
    bqkv[idx] = v;
}

// ---------------- tf32 helpers ----------------
__device__ __forceinline__ uint32_t f2tf(float x) {
    uint32_t r;
    asm("cvt.rna.tf32.f32 %0, %1;" : "=r"(r) : "f"(x));
    return r;
}

__device__ __forceinline__ void mma_tf32(float c[4],
                                         uint32_t a0, uint32_t a1, uint32_t a2, uint32_t a3,
                                         uint32_t b0, uint32_t b1) {
    asm volatile(
        "mma.sync.aligned.m16n8k8.row.col.f32.tf32.tf32.f32 "
        "{%0,%1,%2,%3}, {%4,%5,%6,%7}, {%8,%9}, {%0,%1,%2,%3};"
        : "+f"(c[0]), "+f"(c[1]), "+f"(c[2]), "+f"(c[3])
        : "r"(a0), "r"(a1), "r"(a2), "r"(a3), "r"(b0), "r"(b1));
}

__device__ __forceinline__ uint4 tf_pack(float v0, float v4) {
    uint4 p;
    p.x = f2tf(v0);
    p.y = f2tf(v4);
    p.z = f2tf(v0 - __uint_as_float(p.x));
    p.w = f2tf(v4 - __uint_as_float(p.y));
    return p;
}

// ---------------- bf16 helpers ----------------
// pack2: (x0 -> low half, x1 -> high half)
__device__ __forceinline__ uint32_t bf16pack2(float x0, float x1) {
    uint32_t r;
    asm("cvt.rn.bf16x2.f32 %0, %1, %2;" : "=r"(r) : "f"(x1), "f"(x0));
    return r;
}
// split pair into hi bf16x2 and lo bf16x2 (lo = bf16(x - float(hi)))
__device__ __forceinline__ void bf16split2(float x0, float x1, uint32_t& hi, uint32_t& lo) {
    hi = bf16pack2(x0, x1);
    float h0 = __uint_as_float(hi << 16);
    float h1 = __uint_as_float(hi & 0xFFFF0000u);
    lo = bf16pack2(x0 - h0, x1 - h1);
}

__device__ __forceinline__ void mma_bf16(float c[4],
                                         uint32_t a0, uint32_t a1, uint32_t a2, uint32_t a3,
                                         uint32_t b0, uint32_t b1) {
    asm volatile(
        "mma.sync.aligned.m16n8k16.row.col.f32.bf16.bf16.f32 "
        "{%0,%1,%2,%3}, {%4,%5,%6,%7}, {%8,%9}, {%0,%1,%2,%3};"
        : "+f"(c[0]), "+f"(c[1]), "+f"(c[2]), "+f"(c[3])
        : "r"(a0), "r"(a1), "r"(a2), "r"(a3), "r"(b0), "r"(b1));
}

#define ASTG 576            // 64 rows * 9 uint4
#define BSTG 1152           // 128 rows * 9 uint4
#define GEMM_SMEM (2 * (ASTG + BSTG) * 16)   // double-buffered, bytes (55296)

// ---------------- 3xTF32 GEMM: 64(M)x128(N) tile, double-buffered, 2 blk/SM
template<bool GELU, bool EXPERT, bool GATHER>
__global__ __launch_bounds__(256, 2) void mma_gemm(
    const float* __restrict__ A, const float* __restrict__ B,
    const float* __restrict__ bias, float* __restrict__ C,
    int M, int N, int K, int lda, int ldc,
    const int* __restrict__ perm, const int* __restrict__ offs,
    const int* __restrict__ cnts, size_t strideB, size_t strideBias)
{
    extern __shared__ uint4 sm4[];
    uint4* AP = sm4;                 // [2][ASTG]
    uint4* BP = sm4 + 2 * ASTG;      // [2][BSTG]

    int mcount = M, base = 0;
    if (EXPERT) {
        int e = blockIdx.z;
        mcount = cnts[e];
        base   = offs[e];
        B     += (size_t)e * strideB;
        bias  += (size_t)e * strideBias;
    }
    int m0 = blockIdx.y * 64;
    if (m0 >= mcount) return;
    int n0 = blockIdx.x * 128;

    int tid = threadIdx.x, lane = tid & 31, warp = tid >> 5;
    int wm = (warp & 1) * 32;
    int wn = (warp >> 1) * 32;

    int aRow = tid >> 1;
    int aKK  = tid & 1;
    bool aprod = (tid < 128);
    bool aok = aprod && (m0 + aRow < mcount);
    const float* aptr = A;
    if (aok) {
        int phys = GATHER ? perm[base + m0 + aRow]
                          : (EXPERT ? base + m0 + aRow : m0 + aRow);
        aptr = A + (size_t)phys * (size_t)lda;
    }
    int bN   = tid & 127;
    int bKQ0 = tid >> 7;
    int gn   = n0 + bN;
    bool bok = (gn < N);

    float c[2][4][4];
#pragma unroll
    for (int i = 0; i < 2; i++)
#pragma unroll
        for (int j = 0; j < 4; j++)
#pragma unroll
            for (int q = 0; q < 4; q++) c[i][j][q] = 0.f;

    float stA[8], stB[8];

    if (aprod) {
        float4 v0 = make_float4(0.f,0.f,0.f,0.f), v1 = v0;
        if (aok) {
            v0 = *(const float4*)(aptr + aKK * 8);
            v1 = *(const float4*)(aptr + aKK * 8 + 4);
        }
        stA[0]=v0.x; stA[1]=v0.y; stA[2]=v0.z; stA[3]=v0.w;
        stA[4]=v1.x; stA[5]=v1.y; stA[6]=v1.z; stA[7]=v1.w;
    }
#pragma unroll
    for (int j = 0; j < 4; j++) {
        int kq = bKQ0 + 2 * j;
        int krow = (kq >> 2) * 8 + (kq & 3);
        float b0 = 0.f, b1 = 0.f;
        if (bok) {
            b0 = B[(size_t)krow * (size_t)N + gn];
            b1 = B[(size_t)(krow + 4) * (size_t)N + gn];
        }
        stB[j * 2] = b0; stB[j * 2 + 1] = b1;
    }
    if (aprod) {
#pragma unroll
        for (int q = 0; q < 4; q++)
            AP[aRow * 9 + aKK * 4 + q] = tf_pack(stA[q], stA[q + 4]);
    }
#pragma unroll
    for (int j = 0; j < 4; j++) {
        int kq = bKQ0 + 2 * j;
        BP[bN * 9 + kq] = tf_pack(stB[j * 2], stB[j * 2 + 1]);
    }
    __syncthreads();

    int buf = 0;
    for (int k0 = 0; k0 < K; k0 += 16) {
        bool has_next = (k0 + 16 < K);
        if (has_next) {
            if (aprod) {
                float4 v0 = make_float4(0.f,0.f,0.f,0.f), v1 = v0;
                if (aok) {
                    v0 = *(const float4*)(aptr + k0 + 16 + aKK * 8);
                    v1 = *(const float4*)(aptr + k0 + 16 + aKK * 8 + 4);
                }
                stA[0]=v0.x; stA[1]=v0.y; stA[2]=v0.z; stA[3]=v0.w;
                stA[4]=v1.x; stA[5]=v1.y; stA[6]=v1.z; stA[7]=v1.w;
            }
#pragma unroll
            for (int j = 0; j < 4; j++) {
                int kq = bKQ0 + 2 * j;
                int krow = k0 + 16 + (kq >> 2) * 8 + (kq & 3);
                float b0 = 0.f, b1 = 0.f;
                if (bok) {
                    b0 = B[(size_t)krow * (size_t)N + gn];
                    b1 = B[(size_t)(krow + 4) * (size_t)N + gn];
                }
                stB[j * 2] = b0; stB[j * 2 + 1] = b1;
            }
        }

        const uint4* APc = AP + buf * ASTG;
        const uint4* BPc = BP + buf * BSTG;
        int ra = lane >> 2;
        int q  = lane & 3;
#pragma unroll
        for (int kk = 0; kk < 2; kk++) {
            int kkq = kk * 4 + q;
            uint32_t aH[2][4], aL[2][4];
#pragma unroll
            for (int fm = 0; fm < 2; fm++) {
                int m = wm + fm * 16 + ra;
                uint4 f0 = APc[m * 9 + kkq];
                uint4 f1 = APc[(m + 8) * 9 + kkq];
                aH[fm][0] = f0.x; aH[fm][1] = f1.x;
                aH[fm][2] = f0.y; aH[fm][3] = f1.y;
                aL[fm][0] = f0.z; aL[fm][1] = f1.z;
                aL[fm][2] = f0.w; aL[fm][3] = f1.w;
            }
#pragma unroll
            for (int fn = 0; fn < 4; fn++) {
                int n = wn + fn * 8 + ra;
                uint4 fb = BPc[n * 9 + kkq];
#pragma unroll
                for (int fm = 0; fm < 2; fm++) {
                    mma_tf32(c[fm][fn], aL[fm][0], aL[fm][1], aL[fm][2], aL[fm][3], fb.x, fb.y);
                    mma_tf32(c[fm][fn], aH[fm][0], aH[fm][1], aH[fm][2], aH[fm][3], fb.z, fb.w);
                    mma_tf32(c[fm][fn], aH[fm][0], aH[fm][1], aH[fm][2], aH[fm][3], fb.x, fb.y);
                }
            }
        }

        if (has_next) {
            uint4* APn = AP + (buf ^ 1) * ASTG;
            uint4* BPn = BP + (buf ^ 1) * BSTG;
            if (aprod) {
#pragma unroll
                for (int qq = 0; qq < 4; qq++)
                    APn[aRow * 9 + aKK * 4 + qq] = tf_pack(stA[qq], stA[qq + 4]);
            }
#pragma unroll
            for (int j = 0; j < 4; j++) {
                int kq = bKQ0 + 2 * j;
                BPn[bN * 9 + kq] = tf_pack(stB[j * 2], stB[j * 2 + 1]);
            }
        }
        __syncthreads();
        buf ^= 1;
    }

#pragma unroll
    for (int fm = 0; fm < 2; fm++) {
#pragma unroll
        for (int half = 0; half < 2; half++) {
            int mrel = m0 + wm + fm * 16 + (lane >> 2) + half * 8;
            if (mrel >= mcount) continue;
            size_t crow = (size_t)(EXPERT ? base + mrel : mrel) * (size_t)ldc;
#pragma unroll
            for (int fn = 0; fn < 4; fn++) {
                int n = n0 + wn + fn * 8 + (lane & 3) * 2;
                float v0 = c[fm][fn][half * 2 + 0];
                float v1 = c[fm][fn][half * 2 + 1];
                if (n < N) {
                    float o = v0 + bias[n];
                    if (GELU) o = 0.5f * o * (1.f + erff(o * 0.70710678118654752f));
                    C[crow + n] = o;
                }
                if (n + 1 < N) {
                    float o = v1 + bias[n + 1];
                    if (GELU) o = 0.5f * o * (1.f + erff(o * 0.70710678118654752f));
                    C[crow + n + 1] = o;
                }
            }
        }
    }
}

// ---------------- 2xBF16 GEMM for the final logits projection --------------
// 64(M)x128(N) tile, K-step 16 via m16n8k16, double-buffered.
// uint4 layout per (row, q): (hiPair[k=2q..2q+1], hiPair[k=2q+8..2q+9],
//                             loPair[2q..2q+1],   loPair[2q+8..2q+9])
#define BA_STG (64 * 5)     // uint4 per A stage (320)
#define BB_STG (128 * 5)    // uint4 per B stage (640)
#define GEMM_SMEM_BF (2 * (BA_STG + BB_STG) * 16)   // 30720 bytes

__global__ __launch_bounds__(256, 2) void mma_gemm_bf16(
    const float* __restrict__ A, const float* __restrict__ B,
    const float* __restrict__ bias, float* __restrict__ C,
    int M, int N, int K, int lda, int ldc)
{
    extern __shared__ uint4 sm4[];
    uint4* AP = sm4;                  // [2][BA_STG]
    uint4* BP = sm4 + 2 * BA_STG;     // [2][BB_STG]

    int m0 = blockIdx.y * 64;
    int n0 = blockIdx.x * 128;

    int tid = threadIdx.x, lane = tid & 31, warp = tid >> 5;
    int wm = (warp & 1) * 32;
    int wn = (warp >> 1) * 32;

    // producer A (threads 0..127): row = tid>>1, h2 = tid&1 covers q = 2h2, 2h2+1
    int aRow = tid >> 1;
    int aH2  = tid & 1;
    bool aprod = (tid < 128);
    bool aok = aprod && (m0 + aRow < M);
    const float* aptr = A + (size_t)(m0 + aRow) * (size_t)lda;

    // producer B (all threads): n = tid&127, bH = tid>>7 covers q = 2bH, 2bH+1
    int bN = tid & 127;
    int bH = tid >> 7;
    int gn = n0 + bN;
    bool bok = (gn < N);

    float c[2][4][4];
#pragma unroll
    for (int i = 0; i < 2; i++)
#pragma unroll
        for (int j = 0; j < 4; j++)
#pragma unroll
            for (int q = 0; q < 4; q++) c[i][j][q] = 0.f;

    float sA[8];     // v0(4), v1(4)
    float sB[8];     // per j: b0,b1,b2,b3

    // ---- load tile 0 ----
    if (aprod) {
        float4 v0 = make_float4(0.f,0.f,0.f,0.f), v1 = v0;
        if (aok) {
            v0 = *(const float4*)(aptr + aH2 * 4);
            v1 = *(const float4*)(aptr + aH2 * 4 + 8);
        }
        sA[0]=v0.x; sA[1]=v0.y; sA[2]=v0.z; sA[3]=v0.w;
        sA[4]=v1.x; sA[5]=v1.y; sA[6]=v1.z; sA[7]=v1.w;
    }
#pragma unroll
    for (int j = 0; j < 2; j++) {
        int q = 2 * bH + j;
        int k = 2 * q;
        float b0 = 0.f, b1 = 0.f, b2 = 0.f, b3 = 0.f;
        if (bok) {
            b0 = B[(size_t)k * N + gn];
            b1 = B[(size_t)(k + 1) * N + gn];
            b2 = B[(size_t)(k + 8) * N + gn];
            b3 = B[(size_t)(k + 9) * N + gn];
        }
        sB[j*4+0]=b0; sB[j*4+1]=b1; sB[j*4+2]=b2; sB[j*4+3]=b3;
    }
    // store stage 0
    if (aprod) {
#pragma unroll
        for (int j = 0; j < 2; j++) {
            uint4 p;
            bf16split2(sA[j*2+0], sA[j*2+1], p.x, p.z);
            bf16split2(sA[j*2+4], sA[j*2+5], p.y, p.w);
            AP[aRow * 5 + 2 * aH2 + j] = p;
        }
    }
#pragma unroll
    for (int j = 0; j < 2; j++) {
        uint4 p;
        bf16split2(sB[j*4+0], sB[j*4+1], p.x, p.z);
        bf16split2(sB[j*4+2], sB[j*4+3], p.y, p.w);
        BP[bN * 5 + 2 * bH + j] = p;
    }
    __syncthreads();

    int buf = 0;
    for (int k0 = 0; k0 < K; k0 += 16) {
        bool has_next = (k0 + 16 < K);
        if (has_next) {
            if (aprod) {
                float4 v0 = make_float4(0.f,0.f,0.f,0.f), v1 = v0;
                if (aok) {
                    v0 = *(const float4*)(aptr + k0 + 16 + aH2 * 4);
                    v1 = *(const float4*)(aptr + k0 + 16 + aH2 * 4 + 8);
                }
                sA[0]=v0.x; sA[1]=v0.y; sA[2]=v0.z; sA[3]=v0.w;
                sA[4]=v1.x; sA[5]=v1.y; sA[6]=v1.z; sA[7]=v1.w;
            }
#pragma unroll
            for (int j = 0; j < 2; j++) {
                int q = 2 * bH + j;
                int k = k0 + 16 + 2 * q;
                float b0 = 0.f, b1 = 0.f, b2 = 0.f, b3 = 0.f;
                if (bok) {
                    b0 = B[(size_t)k * N + gn];
                    b1 = B[(size_t)(k + 1) * N + gn];
                    b2 = B[(size_t)(k + 8) * N + gn];
                    b3 = B[(size_t)(k + 9) * N + gn];
                }
                sB[j*4+0]=b0; sB[j*4+1]=b1; sB[j*4+2]=b2; sB[j*4+3]=b3;
            }
        }

        // ---- MMA on stage buf ----
        const uint4* APc = AP + buf * BA_STG;
        const uint4* BPc = BP + buf * BB_STG;
        int ra = lane >> 2;
        int q  = lane & 3;
        uint32_t aHf[2][4], aLf[2][4];
#pragma unroll
        for (int fm = 0; fm < 2; fm++) {
            int m = wm + fm * 16 + ra;
            uint4 f0 = APc[m * 5 + q];
            uint4 f1 = APc[(m + 8) * 5 + q];
            aHf[fm][0] = f0.x; aHf[fm][1] = f1.x;
            aHf[fm][2] = f0.y; aHf[fm][3] = f1.y;
            aLf[fm][0] = f0.z; aLf[fm][1] = f1.z;
            aLf[fm][2] = f0.w; aLf[fm][3] = f1.w;
        }
#pragma unroll
        for (int fn = 0; fn < 4; fn++) {
            int n = wn + fn * 8 + ra;
            uint4 fb = BPc[n * 5 + q];
#pragma unroll
            for (int fm = 0; fm < 2; fm++) {
                mma_bf16(c[fm][fn], aLf[fm][0], aLf[fm][1], aLf[fm][2], aLf[fm][3], fb.x, fb.y);
                mma_bf16(c[fm][fn], aHf[fm][0], aHf[fm][1], aHf[fm][2], aHf[fm][3], fb.z, fb.w);
                mma_bf16(c[fm][fn], aHf[fm][0], aHf[fm][1], aHf[fm][2], aHf[fm][3], fb.x, fb.y);
            }
        }

        if (has_next) {
            uint4* APn = AP + (buf ^ 1) * BA_STG;
            uint4* BPn = BP + (buf ^ 1) * BB_STG;
            if (aprod) {
#pragma unroll
                for (int j = 0; j < 2; j++) {
                    uint4 p;
                    bf16split2(sA[j*2+0], sA[j*2+1], p.x, p.z);
                    bf16split2(sA[j*2+4], sA[j*2+5], p.y, p.w);
                    APn[aRow * 5 + 2 * aH2 + j] = p;
                }
            }
#pragma unroll
            for (int j = 0; j < 2; j++) {
                uint4 p;
                bf16split2(sB[j*4+0], sB[j*4+1], p.x, p.z);
                bf16split2(sB[j*4+2], sB[j*4+3], p.y, p.w);
                BPn[bN * 5 + 2 * bH + j] = p;
            }
        }
        __syncthreads();
        buf ^= 1;
    }

    // epilogue (same C layout as tf32 m16n8)
#pragma unroll
    for (int fm = 0; fm < 2; fm++) {
#pragma unroll
        for (int half = 0; half < 2; half++) {
            int mrel = m0 + wm + fm * 16 + (lane >> 2) + half * 8;
            if (mrel >= M) continue;
            size_t crow = (size_t)mrel * (size_t)ldc;
#pragma unroll
            for (int fn = 0; fn < 4; fn++) {
                int n = n0 + wn + fn * 8 + (lane & 3) * 2;
                if (n < N)     C[crow + n]     = c[fm][fn][half * 2 + 0] + bias[n];
                if (n + 1 < N) C[crow + n + 1] = c[fm][fn][half * 2 + 1] + bias[n + 1];
            }
        }
    }
}

// ---------------- flash-style GQA attention (fp32, reads combined QKV) ----------------
__global__ __launch_bounds__(256) void attn_kernel(
    const float* __restrict__ qkv, const int* __restrict__ amask,
    float* __restrict__ ao)
{
    const float SCALE = 0.125f;
    int head = blockIdx.y;
    int g    = head / (NHD / NG);
    int q0   = blockIdx.x * 64;

    __shared__ float QsT[64][68];
    __shared__ float KsT[64][33];
    __shared__ float Vs [32][68];
    __shared__ float PsT[32][68];
    __shared__ float Mk [32];

    int tid = threadIdx.x;
#pragma unroll
    for (int i = 0; i < 4; i++) {
        int idx = tid + i * 256;
        int r = idx >> 4;
        int dseg = (idx & 15) * 4;
        float4 qv = *(const float4*)(qkv + (size_t)(q0 + r) * QKVN + head * 64 + dseg);
        QsT[dseg + 0][r] = qv.x; QsT[dseg + 1][r] = qv.y;
        QsT[dseg + 2][r] = qv.z; QsT[dseg + 3][r] = qv.w;
    }

    int rg = tid >> 4, kg = tid & 15;
    int r0 = rg * 4, d0 = kg * 4, j0 = kg * 2;

    float acc[4][4] = {};
    float m[4], l[4];
#pragma unroll
    for (int i = 0; i < 4; i++) { m[i] = -3.0e38f; l[i] = 0.f; }

    for (int kc = 0; kc < 32; kc++) {
        int kbase = kc * 32;
#pragma unroll
        for (int i = 0; i < 2; i++) {
            int idx = tid + i * 256;
            int kk = idx >> 4;
            int dseg = (idx & 15) * 4;
            float4 kv = *(const float4*)(qkv + (size_t)(kbase + kk) * QKVN + HID + g * 64 + dseg);
            KsT[dseg + 0][kk] = kv.x; KsT[dseg + 1][kk] = kv.y;
            KsT[dseg + 2][kk] = kv.z; KsT[dseg + 3][kk] = kv.w;
            float4 vv = *(const float4*)(qkv + (size_t)(kbase + kk) * QKVN + HID + 256 + g * 64 + dseg);
            *(float4*)&Vs[kk][dseg] = vv;
        }
        if (tid < 32) Mk[tid] = (amask[kbase + tid] == 0) ? -3.0e38f : 0.f;
        __syncthreads();

        float s0[4] = {}, s1[4] = {};
#pragma unroll
        for (int d = 0; d < 64; d++) {
            float4 a = *(const float4*)&QsT[d][r0];
            float b0 = KsT[d][j0], b1 = KsT[d][j0 + 1];
            s0[0] += a.x * b0; s1[0] += a.x * b1;
            s0[1] += a.y * b0; s1[1] += a.y * b1;
            s0[2] += a.z * b0; s1[2] += a.z * b1;
            s0[3] += a.w * b0; s1[3] += a.w * b1;
        }
        float mk0 = Mk[j0], mk1 = Mk[j0 + 1];
        float cm[4];
#pragma unroll
        for (int i = 0; i < 4; i++) {
            s0[i] = s0[i] * SCALE + mk0;
            s1[i] = s1[i] * SCALE + mk1;
            cm[i] = fmaxf(s0[i], s1[i]);
        }
#pragma unroll
        for (int o = 1; o < 16; o <<= 1)
#pragma unroll
            for (int i = 0; i < 4; i++)
                cm[i] = fmaxf(cm[i], __shfl_xor_sync(0xffffffffu, cm[i], o));

        float p0[4], p1[4], csum[4];
#pragma unroll
        for (int i = 0; i < 4; i++) {
            float nm = fmaxf(m[i], cm[i]);
            float alpha = expf(m[i] - nm);
            m[i] = nm;
            p0[i] = expf(s0[i] - nm);
            p1[i] = expf(s1[i] - nm);
            csum[i] = p0[i] + p1[i];
            l[i] *= alpha;
#pragma unroll
            for (int j = 0; j < 4; j++) acc[i][j] *= alpha;
        }
#pragma unroll
        for (int o = 1; o < 16; o <<= 1)
#pragma unroll
            for (int i = 0; i < 4; i++)
                csum[i] += __shfl_xor_sync(0xffffffffu, csum[i], o);
#pragma unroll
        for (int i = 0; i < 4; i++) l[i] += csum[i];

#pragma unroll
        for (int i = 0; i < 4; i++) {
            PsT[j0][r0 + i]     = p0[i];
            PsT[j0 + 1][r0 + i] = p1[i];
        }
        __syncthreads();

#pragma unroll
        for (int key = 0; key < 32; key++) {
            float4 pv = *(const float4*)&PsT[key][r0];
            float4 vv = *(const float4*)&Vs[key][d0];
            acc[0][0] += pv.x * vv.x; acc[0][1] += pv.x * vv.y; acc[0][2] += pv.x * vv.z; acc[0][3] += pv.x * vv.w;
            acc[1][0] += pv.y * vv.x; acc[1][1] += pv.y * vv.y; acc[1][2] += pv.y * vv.z; acc[1][3] += pv.y * vv.w;
            acc[2][0] += pv.z * vv.x; acc[2][1] += pv.z * vv.y; acc[2][2] += pv.z * vv.z; acc[2][3] += pv.z * vv.w;
            acc[3][0] += pv.w * vv.x; acc[3][1] += pv.w * vv.y; acc[3][2] += pv.w * vv.z; acc[3][3] += pv.w * vv.w;
        }
        __syncthreads();
    }

#pragma unroll
    for (int i = 0; i < 4; i++) {
        float inv = 1.f / l[i];
        float4 o;
        o.x = acc[i][0] * inv; o.y = acc[i][1] * inv;
        o.z = acc[i][2] * inv; o.w = acc[i][3] * inv;
        *(float4*)(ao + (size_t)(q0 + r0 + i) * HID + head * 64 + d0) = o;
    }
}

// ---------------- layernorm: h = LN(h + res) ----------------
__global__ __launch_bounds__(256) void ln_kernel(float* __restrict__ h,
                                                 const float* __restrict__ res,
                                                 const float* __restrict__ gam,
                                                 const float* __restrict__ bet) {
    int row = blockIdx.x;
    __shared__ float xbuf[HID];
    __shared__ float red[256];
    int tid = threadIdx.x;
    float lsum = 0.f;
    for (int c = tid; c < HID; c += 256) {
        float v = h[(size_t)row * HID + c] + res[(size_t)row * HID + c];
        xbuf[c] = v;
        lsum += v;
    }
    red[tid] = lsum; __syncthreads();
    for (int s = 128; s > 0; s >>= 1) { if (tid < s) red[tid] += red[tid + s]; __syncthreads(); }
    float mean = red[0] / (float)HID;
    __syncthreads();
    float lvar = 0.f;
    for (int c = tid; c < HID; c += 256) { float d = xbuf[c] - mean; lvar += d * d; }
    red[tid] = lvar; __syncthreads();
    for (int s = 128; s > 0; s >>= 1) { if (tid < s) red[tid] += red[tid + s]; __syncthreads(); }
    float rstd = rsqrtf(red[0] / (float)HID + 1e-5f);
    for (int c = tid; c < HID; c += 256)
        h[(size_t)row * HID + c] = (xbuf[c] - mean) * rstd * gam[c] + bet[c];
}

// ---------------- router: top-2 gating ----------------
__global__ __launch_bounds__(256) void router_kernel(
    const float* __restrict__ h, const float* __restrict__ rw,
    const float* __restrict__ rb, float* __restrict__ gates,
    int* __restrict__ texp, int* __restrict__ tlocal, int* __restrict__ cnt)
{
    int t = blockIdx.x;
    int tid = threadIdx.x;
    int e = tid >> 5, lane = tid & 31;
    float sum = 0.f;
    for (int i = lane; i < HID; i += 32)
        sum += h[(size_t)t * HID + i] * rw[i * NEXP + e];
#pragma unroll
    for (int o = 16; o > 0; o >>= 1) sum += __shfl_down_sync(0xffffffffu, sum, o);
    __shared__ float logits[NEXP];
    if (lane == 0) logits[e] = sum + rb[e];
    __syncthreads();
    if (tid == 0) {
        float mx = logits[0];
        for (int i = 1; i < NEXP; i++) mx = fmaxf(mx, logits[i]);
        float ex[NEXP], ssum = 0.f;
        for (int i = 0; i < NEXP; i++) { ex[i] = expf(logits[i] - mx); ssum += ex[i]; }
        float p[NEXP];
        for (int i = 0; i < NEXP; i++) p[i] = ex[i] / ssum;
        int i0 = 0;
        for (int i = 1; i < NEXP; i++) if (p[i] > p[i0]) i0 = i;
        int i1 = (i0 == 0) ? 1 : 0;
        for (int i = 0; i < NEXP; i++) if (i != i0 && p[i] > p[i1]) i1 = i;
        float b = expf(p[i1] - p[i0]);
        float g0 = 1.f / (1.f + b);
        float g1 = b / (1.f + b);
        gates[t * 2] = g0; gates[t * 2 + 1] = g1;
        texp[t * 2] = i0; texp[t * 2 + 1] = i1;
        tlocal[t * 2]     = atomicAdd(&cnt[i0], 1);
        tlocal[t * 2 + 1] = atomicAdd(&cnt[i1], 1);
    }
}

__global__ void zero_cnt_kernel(int* c) { if (threadIdx.x < NEXP) c[threadIdx.x] = 0; }

__global__ __launch_bounds__(256) void assign_kernel(
    const int* __restrict__ cnt, int* __restrict__ offs, int* __restrict__ perm,
    const int* __restrict__ texp, const int* __restrict__ tlocal,
    int* __restrict__ tslot, int* __restrict__ loads)
{
    __shared__ int so[NEXP];
    if (threadIdx.x == 0) {
        int acc = 0;
        for (int e = 0; e < NEXP; e++) {
            so[e] = acc; offs[e] = acc; loads[e] = cnt[e]; acc += cnt[e];
        }
    }
    __syncthreads();
    for (int i = threadIdx.x; i < 2 * SQ; i += blockDim.x) {
        int t = i >> 1;
        int slot = so[texp[i]] + tlocal[i];
        perm[slot] = t;
        tslot[i] = slot;
    }
}

__global__ __launch_bounds__(256) void combine_kernel(
    const float* __restrict__ eo, const float* __restrict__ gates,
    const int* __restrict__ tslot, float* __restrict__ res)
{
    int t = blockIdx.x;
    int s0 = tslot[t * 2], s1 = tslot[t * 2 + 1];
    float g0 = gates[t * 2], g1 = gates[t * 2 + 1];
    for (int c = threadIdx.x; c < HID; c += 256)
        res[(size_t)t * HID + c] = g0 * eo[(size_t)s0 * HID + c] + g1 * eo[(size_t)s1 * HID + c];
}

__global__ void loss_kernel(const int* __restrict__ loads, float* __restrict__ out) {
    int l = threadIdx.x;
    if (l < NLAY) {
        float mean = (float)(2 * SQ) / (float)NEXP;
        float var = 0.f;
        for (int e = 0; e < NEXP; e++) {
            float d = (float)loads[l * NEXP + e] - mean;
            var += d * d;
        }
        var /= (float)(NEXP - 1);
        out[l] = var / (mean * mean);
    }
}

// ---------------- host launch ----------------
static void launch_gemm(const float* A, const float* B, const float* bias,
                        float* C, int M, int N, int K, int lda, int ldc) {
    dim3 grid((N + 127) / 128, (M + 63) / 64);
    mma_gemm<false, false, false><<<grid, 256, GEMM_SMEM>>>(
        A, B, bias, C, M, N, K, lda, ldc, nullptr, nullptr, nullptr, 0, 0);
}

extern "C" void kernel_launch(void* const* d_in, const int* in_sizes, int n_in,
                              void* d_out, int out_size) {
    const int*   ids   = (const int*)d_in[0];
    const int*   amask = (const int*)d_in[1];
    const float* emb   = (const float*)d_in[2];
    const float* pos   = (const float*)d_in[3];
    const float* qw    = (const float*)d_in[4];
    const float* qb    = (const float*)d_in[5];
    const float* kw    = (const float*)d_in[6];
    const float* kb    = (const float*)d_in[7];
    const float* vw    = (const float*)d_in[8];
    const float* vb    = (const float*)d_in[9];
    const float* rw    = (const float*)d_in[10];
    const float* rb    = (const float*)d_in[11];
    const float* fc1w  = (const float*)d_in[12];
    const float* fc1b  = (const float*)d_in[13];
    const float* fc2w  = (const float*)d_in[14];
    const float* fc2b  = (const float*)d_in[15];
    const float* lng   = (const float*)d_in[16];
    const float* lnb   = (const float*)d_in[17];
    const float* ow    = (const float*)d_in[18];
    const float* ob    = (const float*)d_in[19];
    float* out = (float*)d_out;

    cudaFuncSetAttribute(mma_gemm<false, false, false>,
                         cudaFuncAttributeMaxDynamicSharedMemorySize, GEMM_SMEM);
    cudaFuncSetAttribute(mma_gemm<true, true, true>,
                         cudaFuncAttributeMaxDynamicSharedMemorySize, GEMM_SMEM);
    cudaFuncSetAttribute(mma_gemm<false, true, false>,
                         cudaFuncAttributeMaxDynamicSharedMemorySize, GEMM_SMEM);
    cudaFuncSetAttribute(mma_gemm_bf16,
                         cudaFuncAttributeMaxDynamicSharedMemorySize, GEMM_SMEM_BF);

    float *h, *res, *qkv, *wqkv, *bqkv, *h1, *eo, *gates;
    int *texp, *tlocal, *tslot, *cnt, *offs, *perm, *loads;
    cudaGetSymbolAddress((void**)&h, g_h);
    cudaGetSymbolAddress((void**)&res, g_res);
    cudaGetSymbolAddress((void**)&qkv, g_qkv);
    cudaGetSymbolAddress((void**)&wqkv, g_wqkv);
    cudaGetSymbolAddress((void**)&bqkv, g_bqkv);
    cudaGetSymbolAddress((void**)&h1, g_h1);
    cudaGetSymbolAddress((void**)&eo, g_eo);
    cudaGetSymbolAddress((void**)&gates, g_gates);
    cudaGetSymbolAddress((void**)&texp, g_texp);
    cudaGetSymbolAddress((void**)&tlocal, g_tlocal);
    cudaGetSymbolAddress((void**)&tslot, g_tslot);
    cudaGetSymbolAddress((void**)&cnt, g_cnt);
    cudaGetSymbolAddress((void**)&offs, g_offs);
    cudaGetSymbolAddress((void**)&perm, g_perm);
    cudaGetSymbolAddress((void**)&loads, g_loads);

    {
        size_t tot = (size_t)NLAY * HID * QKVN;
        pack_qkv_w<<<(unsigned)((tot + 255) / 256), 256>>>(qw, kw, vw, wqkv);
        pack_qkv_b<<<(NLAY * QKVN + 255) / 256, 256>>>(qb, kb, vb, bqkv);
    }

    embed_kernel<<<SQ, 256>>>(ids, emb, pos, h);

    for (int l = 0; l < NLAY; l++) {
        const float* rw_l = rw + (size_t)l * HID * NEXP;
        const float* rb_l = rb + (size_t)l * NEXP;
        const float* fc1w_l = fc1w + (size_t)l * NEXP * HID * FFD;
        const float* fc1b_l = fc1b + (size_t)l * NEXP * FFD;
        const float* fc2w_l = fc2w + (size_t)l * NEXP * FFD * HID;
        const float* fc2b_l = fc2b + (size_t)l * NEXP * HID;

        // fused QKV projection: [1024,768] @ [768,1280]
        launch_gemm(h, wqkv + (size_t)l * HID * QKVN, bqkv + (size_t)l * QKVN,
                    qkv, SQ, QKVN, HID, HID, QKVN);

        attn_kernel<<<dim3(SQ / 64, NHD), 256>>>(qkv, amask, res);
        ln_kernel<<<SQ, 256>>>(h, res, lng, lnb);

        zero_cnt_kernel<<<1, 32>>>(cnt);
        router_kernel<<<SQ, 256>>>(h, rw_l, rb_l, gates, texp, tlocal, cnt);
        assign_kernel<<<1, 256>>>(cnt, offs, perm, texp, tlocal, tslot, loads + l * NEXP);

        {   // fc1 + gelu (gathered rows)
            dim3 grid(FFD / 128, SQ / 64, NEXP);
            mma_gemm<true, true, true><<<grid, 256, GEMM_SMEM>>>(
                h, fc1w_l, fc1b_l, h1, SQ, FFD, HID, HID, FFD,
                perm, offs, cnt, (size_t)HID * FFD, (size_t)FFD);
        }
        {   // fc2 (contiguous slots)
            dim3 grid(HID / 128, SQ / 64, NEXP);
            mma_gemm<false, true, false><<<grid, 256, GEMM_SMEM>>>(
                h1, fc2w_l, fc2b_l, eo, SQ, HID, FFD, FFD, HID,
                nullptr, offs, cnt, (size_t)FFD * HID, (size_t)HID);
        }
        combine_kernel<<<SQ, 256>>>(eo, gates, tslot, res);
        ln_kernel<<<SQ, 256>>>(h, res, lng, lnb);
    }

    // final logits projection with 2xBF16 split (post-routing: safe)
    {
        dim3 grid((NVOC + 127) / 128, SQ / 64);
        mma_gemm_bf16<<<grid, 256, GEMM_SMEM_BF>>>(
            h, ow, ob, out, SQ, NVOC, HID, HID, NVOC);
    }
    loss_kernel<<<1, 32>>>(loads, out + ((size_t)out_size - NLAY));
}